// round 14
// baseline (speedup 1.0000x reference)
#include <cuda_runtime.h>
#include <cuda_bf16.h>
#include <math.h>
#include <stdint.h>

#define EMBED   128
#define VDIM    50257
#define VPAD    50304                 // 786 * 64
#define NSTEP   128
#define BATCH   32
#define ROWS    (BATCH*NSTEP)         // 4096
#define NSPLIT  13
#define NTILE   64
#define NTILES_TOTAL (VPAD/NTILE)     // 786
#define BSTRIDE 136                   // bf16 elems per padded row (272 B)
#define LOG2E_F 1.4426950408889634f

// ---------------- scratch (static device globals: no allocation) ------------
__device__ __nv_bfloat16 g_Wvb[(size_t)VPAD * EMBED];   // Wv in bf16, zero-padded rows
__device__ float         g_bv2[VPAD];                   // bv * log2(e), pad = -1e30
__device__ float         g_zs [ROWS * EMBED];           // fp32 states (for exact l_y)
__device__ __nv_bfloat16 g_zsb[ROWS * EMBED];           // bf16 states (GEMM A)
__device__ float         g_ly [ROWS];                   // gathered logit (fp32 exact)
__device__ float         g_S  [NSPLIT * ROWS];          // per-split sum(exp(l))

// two exp2's for one MUFU op: pack to f16x2, ex2.approx.f16x2, unpack+add.
// pad inputs (-1e30) saturate to -inf in f16 -> exp2 = 0 (correct).
__device__ __forceinline__ float ex2_pair_sum(float a, float b) {
    unsigned p;
    asm("{ .reg .b32 t;\n\t"
        "cvt.rn.f16x2.f32 t, %1, %2;\n\t"
        "ex2.approx.f16x2 t, t;\n\t"
        "mov.b32 %0, t; }" : "=r"(p) : "f"(a), "f"(b));
    float lo, hi;
    asm("{ .reg .f16 l, h;\n\t"
        "mov.b32 {l, h}, %2;\n\t"
        "cvt.f32.f16 %0, l;\n\t"
        "cvt.f32.f16 %1, h; }" : "=f"(lo), "=f"(hi) : "r"(p));
    return lo + hi;
}

// ---------------- kernel 0: convert Wv -> bf16 (padded), bv -> bv*log2e -----
__global__ void convert_kernel(const float* __restrict__ Wv,
                               const float* __restrict__ bv) {
    int idx = blockIdx.x * blockDim.x + threadIdx.x;
    const int total = VPAD * EMBED;
    if (idx < total) {
        int row = idx >> 7;
        float v = (row < VDIM) ? Wv[idx] : 0.0f;
        g_Wvb[idx] = __float2bfloat16(v);
    }
    if (idx < VPAD) {
        g_bv2[idx] = (idx < VDIM) ? bv[idx] * LOG2E_F : -1e30f;
    }
}

// ---------------- kernel 1: RNN rollout ------------------------------------
// one CTA per batch element, 128 threads; Wt row register-resident.
__global__ void __launch_bounds__(EMBED, 1) rnn_kernel(const int*   __restrict__ zi,
                                                       const float* __restrict__ latent,
                                                       const float* __restrict__ Wt,
                                                       const float* __restrict__ bt) {
    int b = blockIdx.x;
    int e = threadIdx.x;
    __shared__ float zb[2][EMBED];

    float w[EMBED];
    {
        const float4* wrow = reinterpret_cast<const float4*>(Wt + e * EMBED);
        #pragma unroll
        for (int k = 0; k < EMBED / 4; k++) {
            float4 w4 = __ldg(wrow + k);
            w[4*k+0] = w4.x; w[4*k+1] = w4.y; w[4*k+2] = w4.z; w[4*k+3] = w4.w;
        }
    }

    float z   = latent[zi[b] * EMBED + e];
    float bte = bt[e];
    zb[0][e] = z;
    __syncthreads();

    for (int t = 0; t < NSTEP; t++) {
        int cur = t & 1;
        float zc = zb[cur][e];
        int o = (b * NSTEP + t) * EMBED + e;
        g_zs [o] = zc;                       // emit BEFORE update (scan semantics)
        g_zsb[o] = __float2bfloat16(zc);

        const float4* zv = reinterpret_cast<const float4*>(zb[cur]);
        float a0 = 0.f, a1 = 0.f, a2 = 0.f, a3 = 0.f;
        #pragma unroll
        for (int k = 0; k < EMBED / 4; k++) {
            float4 z4 = zv[k];               // broadcast LDS
            a0 = fmaf(w[4*k+0], z4.x, a0);
            a1 = fmaf(w[4*k+1], z4.y, a1);
            a2 = fmaf(w[4*k+2], z4.z, a2);
            a3 = fmaf(w[4*k+3], z4.w, a3);
        }
        float zn = tanhf(zc + (a0 + a1) + (a2 + a3) + bte);
        zb[cur ^ 1][e] = zn;
        __syncthreads();
    }
}

// ---------------- kernel 2: fused logits GEMM + sum(exp) --------------------
// R13 body unchanged. TWO launch-config changes:
//  * __launch_bounds__(128, 3): 170-reg cap -> 3 CTAs/SM (12 warps, 3/SMSP).
//    Hot set Afrag(64)+d(64)+sums(4)+misc ~160 < 170 -> no spills expected.
//    R13 profile: occ=12% (2 warps/SMSP) left 33% of tensor idle on latency.
//  * NSPLIT 13 -> grid 416 so ~2.8 CTAs/SM actually co-reside in one wave.
__global__ void __launch_bounds__(128, 3) lse_kernel() {
    __shared__ __align__(16) __nv_bfloat16 Bs[2][NTILE * BSTRIDE];
    __shared__ __align__(16) float bvs[2][NTILE];

    const int tid  = threadIdx.x;
    const int w    = tid >> 5;      // 0..3
    const int lane = tid & 31;
    const int g    = lane >> 2;     // 0..7
    const int q    = lane & 3;      // 0..3
    const int rt   = blockIdx.x;
    const int sp   = blockIdx.y;

    // ---- A fragments: 2 m16-tiles x 8 k-steps x 4 regs = 64 regs, resident
    unsigned Afrag[2][8][4];
    {
        const __nv_bfloat16* Z = g_zsb;
        #pragma unroll
        for (int mt = 0; mt < 2; mt++) {
            int r0 = (rt * 128 + w * 32 + mt * 16 + g) * EMBED;
            int r1 = r0 + 8 * EMBED;
            #pragma unroll
            for (int s = 0; s < 8; s++) {
                int k0 = s * 16 + 2 * q;
                Afrag[mt][s][0] = *reinterpret_cast<const unsigned*>(Z + r0 + k0);
                Afrag[mt][s][1] = *reinterpret_cast<const unsigned*>(Z + r1 + k0);
                Afrag[mt][s][2] = *reinterpret_cast<const unsigned*>(Z + r0 + k0 + 8);
                Afrag[mt][s][3] = *reinterpret_cast<const unsigned*>(Z + r1 + k0 + 8);
            }
        }
    }

    const unsigned sbase  = (unsigned)__cvta_generic_to_shared(&Bs[0][0]);
    const unsigned bvbase = (unsigned)__cvta_generic_to_shared(&bvs[0][0]);

    const int count = (NTILES_TOTAL - sp + NSPLIT - 1) / NSPLIT;

    auto issue = [&](int i, int buf) {
        int vbase = (sp + i * NSPLIT) * NTILE;
        const __nv_bfloat16* src0 = g_Wvb + (size_t)vbase * EMBED;
        #pragma unroll
        for (int c = 0; c < 8; c++) {
            int ch = tid + c * 128;          // 0..1023 16B chunks
            int vr = ch >> 4;
            int kc = ch & 15;
            unsigned dst = sbase + buf * (NTILE * BSTRIDE * 2)
                         + (vr * BSTRIDE + kc * 8) * 2;
            const void* src = src0 + vr * EMBED + kc * 8;
            asm volatile("cp.async.cg.shared.global [%0], [%1], 16;\n"
                         :: "r"(dst), "l"(src));
        }
        if (tid < 16) {
            unsigned dst = bvbase + buf * (NTILE * 4) + tid * 16;
            const void* src = g_bv2 + vbase + tid * 4;
            asm volatile("cp.async.cg.shared.global [%0], [%1], 16;\n"
                         :: "r"(dst), "l"(src));
        }
        asm volatile("cp.async.commit_group;\n");
    };

    float sum[2][2] = {{0.f, 0.f}, {0.f, 0.f}};

    issue(0, 0);
    for (int i = 0; i < count; i++) {
        const int buf = i & 1;
        if (i + 1 < count) {
            issue(i + 1, buf ^ 1);
            asm volatile("cp.async.wait_group 1;\n" ::: "memory");
        } else {
            asm volatile("cp.async.wait_group 0;\n" ::: "memory");
        }
        __syncthreads();

        float d[2][8][4];
        #pragma unroll
        for (int mt = 0; mt < 2; mt++)
            #pragma unroll
            for (int j = 0; j < 8; j++) {
                d[mt][j][0] = 0.f; d[mt][j][1] = 0.f;
                d[mt][j][2] = 0.f; d[mt][j][3] = 0.f;
            }

        const unsigned rowoff  = (unsigned)((lane & 7) * (BSTRIDE * 2) + (lane >> 3) * 16);
        const unsigned bufbase = sbase + buf * (NTILE * BSTRIDE * 2) + rowoff;

        #pragma unroll
        for (int s2 = 0; s2 < 4; s2++) {        // k32 chunks
            #pragma unroll
            for (int j = 0; j < 8; j++) {       // n8 groups
                unsigned b0, b1, b2, b3;
                asm volatile(
                    "ldmatrix.sync.aligned.m8n8.x4.shared.b16 {%0,%1,%2,%3}, [%4];\n"
                    : "=r"(b0), "=r"(b1), "=r"(b2), "=r"(b3)
                    : "r"(bufbase + (unsigned)(j * 8 * (BSTRIDE * 2)) + s2 * 64));
                #pragma unroll
                for (int mt = 0; mt < 2; mt++) {
                    asm volatile(
                        "mma.sync.aligned.m16n8k16.row.col.f32.bf16.bf16.f32 "
                        "{%0,%1,%2,%3}, {%4,%5,%6,%7}, {%8,%9}, {%0,%1,%2,%3};\n"
                        : "+f"(d[mt][j][0]), "+f"(d[mt][j][1]),
                          "+f"(d[mt][j][2]), "+f"(d[mt][j][3])
                        : "r"(Afrag[mt][2*s2][0]), "r"(Afrag[mt][2*s2][1]),
                          "r"(Afrag[mt][2*s2][2]), "r"(Afrag[mt][2*s2][3]),
                          "r"(b0), "r"(b1));
                    asm volatile(
                        "mma.sync.aligned.m16n8k16.row.col.f32.bf16.bf16.f32 "
                        "{%0,%1,%2,%3}, {%4,%5,%6,%7}, {%8,%9}, {%0,%1,%2,%3};\n"
                        : "+f"(d[mt][j][0]), "+f"(d[mt][j][1]),
                          "+f"(d[mt][j][2]), "+f"(d[mt][j][3])
                        : "r"(Afrag[mt][2*s2+1][0]), "r"(Afrag[mt][2*s2+1][1]),
                          "r"(Afrag[mt][2*s2+1][2]), "r"(Afrag[mt][2*s2+1][3]),
                          "r"(b2), "r"(b3));
                }
            }
        }

        // epilogue: logits -> sum of exp2 (f16x2 MUFU, 2 exps/op)
        #pragma unroll
        for (int j = 0; j < 8; j++) {
            float bva = bvs[buf][j * 8 + 2 * q];
            float bvb = bvs[buf][j * 8 + 2 * q + 1];
            #pragma unroll
            for (int mt = 0; mt < 2; mt++) {
                sum[mt][0] += ex2_pair_sum(fmaf(d[mt][j][0], LOG2E_F, bva),
                                           fmaf(d[mt][j][1], LOG2E_F, bvb));
                sum[mt][1] += ex2_pair_sum(fmaf(d[mt][j][2], LOG2E_F, bva),
                                           fmaf(d[mt][j][3], LOG2E_F, bvb));
            }
        }
        __syncthreads();
    }

    // reduce over the 4 q-threads holding the same rows
    #pragma unroll
    for (int mt = 0; mt < 2; mt++) {
        float s0 = sum[mt][0], s1 = sum[mt][1];
        s0 += __shfl_xor_sync(0xffffffffu, s0, 1);
        s0 += __shfl_xor_sync(0xffffffffu, s0, 2);
        s1 += __shfl_xor_sync(0xffffffffu, s1, 1);
        s1 += __shfl_xor_sync(0xffffffffu, s1, 2);
        if (q == 0) {
            int r = rt * 128 + w * 32 + mt * 16 + g;
            g_S[sp * ROWS + r]     = s0;
            g_S[sp * ROWS + r + 8] = s1;
        }
    }
}

// ---------------- kernel 3: gathered logit l_y (exact fp32) -----------------
__global__ void __launch_bounds__(256) ly_kernel(const int*   __restrict__ y,
                                                 const float* __restrict__ Wv,
                                                 const float* __restrict__ bv) {
    int gw   = (blockIdx.x * blockDim.x + threadIdx.x) >> 5;  // 0..4095
    int lane = threadIdx.x & 31;
    int col  = y[gw];
    const float4* zz = reinterpret_cast<const float4*>(g_zs) + gw * 32 + lane;
    const float4* ww = reinterpret_cast<const float4*>(Wv) + (size_t)col * 32 + lane;
    float4 a = *zz;
    float4 bb = __ldg(ww);
    float p = a.x * bb.x + a.y * bb.y + a.z * bb.z + a.w * bb.w;
    #pragma unroll
    for (int o = 16; o; o >>= 1) p += __shfl_xor_sync(0xffffffffu, p, o);
    if (lane == 0) g_ly[gw] = p + bv[col];
}

// ---------------- kernel 4: combine -----------------------------------------
__global__ void combine_kernel(float* __restrict__ out) {
    int r = blockIdx.x * blockDim.x + threadIdx.x;
    if (r < ROWS) {
        float s = 0.f;
        #pragma unroll
        for (int i = 0; i < NSPLIT; i++) s += g_S[i * ROWS + r];
        out[r] = g_ly[r] - logf(s);
    }
}

// ---------------- launch -----------------------------------------------------
extern "C" void kernel_launch(void* const* d_in, const int* in_sizes, int n_in,
                              void* d_out, int out_size) {
    const int*   zi     = (const int*)  d_in[0];
    const int*   y      = (const int*)  d_in[1];
    const float* latent = (const float*)d_in[2];
    const float* Wt     = (const float*)d_in[3];
    const float* bt     = (const float*)d_in[4];
    const float* Wv     = (const float*)d_in[5];
    const float* bv     = (const float*)d_in[6];
    float* out = (float*)d_out;

    convert_kernel<<<(VPAD * EMBED + 255) / 256, 256>>>(Wv, bv);
    rnn_kernel<<<BATCH, EMBED>>>(zi, latent, Wt, bt);
    ly_kernel<<<ROWS / 8, 256>>>(y, Wv, bv);
    lse_kernel<<<dim3(32, NSPLIT), 128>>>();
    combine_kernel<<<(ROWS + 255) / 256, 256>>>(out);
}

// round 16
// speedup vs baseline: 1.1313x; 1.1313x over previous
#include <cuda_runtime.h>
#include <cuda_fp16.h>
#include <math.h>
#include <stdint.h>

#define EMBED   128
#define VDIM    50257
#define VPAD    50304                 // 786 * 64
#define NSTEP   128
#define BATCH   32
#define ROWS    (BATCH*NSTEP)         // 4096
#define NSPLIT  14
#define NTILE   64
#define NTILES_TOTAL (VPAD/NTILE)     // 786
#define BSTRIDE 136                   // f16 elems per padded row (272 B)
#define LOG2E_F 1.4426950408889634f

// ---------------- scratch (static device globals: no allocation) ------------
__device__ __half  g_Wvh[(size_t)VPAD * EMBED];   // Wv in fp16, zero-padded rows
__device__ __half  g_bvh[VPAD];                   // bv * log2(e) in fp16, pad -20000
__device__ float   g_zs [ROWS * EMBED];           // fp32 states (for exact l_y)
__device__ __half  g_zsh[ROWS * EMBED];           // fp16 states (GEMM A)
__device__ float   g_ly [ROWS];                   // gathered logit (fp32 exact)
__device__ float   g_S  [NSPLIT * ROWS];          // per-split sum(exp(l))

// ex2.approx.f16x2 on packed pair
__device__ __forceinline__ unsigned ex2_h2(unsigned x) {
    unsigned y;
    asm("ex2.approx.f16x2 %0, %1;" : "=r"(y) : "r"(x));
    return y;
}

// ---------------- kernel 0: convert Wv -> fp16 (padded), bv -> fp16*log2e ---
__global__ void convert_kernel(const float* __restrict__ Wv,
                               const float* __restrict__ bv) {
    int idx = blockIdx.x * blockDim.x + threadIdx.x;
    const int total = VPAD * EMBED;
    if (idx < total) {
        int row = idx >> 7;
        float v = (row < VDIM) ? Wv[idx] : 0.0f;
        g_Wvh[idx] = __float2half(v);
    }
    if (idx < VPAD) {
        g_bvh[idx] = __float2half((idx < VDIM) ? bv[idx] * LOG2E_F : -20000.0f);
    }
}

// ---------------- kernel 1: RNN rollout ------------------------------------
// one CTA per batch element, 128 threads; Wt row register-resident.
__global__ void __launch_bounds__(EMBED, 1) rnn_kernel(const int*   __restrict__ zi,
                                                       const float* __restrict__ latent,
                                                       const float* __restrict__ Wt,
                                                       const float* __restrict__ bt) {
    int b = blockIdx.x;
    int e = threadIdx.x;
    __shared__ float zb[2][EMBED];

    float w[EMBED];
    {
        const float4* wrow = reinterpret_cast<const float4*>(Wt + e * EMBED);
        #pragma unroll
        for (int k = 0; k < EMBED / 4; k++) {
            float4 w4 = __ldg(wrow + k);
            w[4*k+0] = w4.x; w[4*k+1] = w4.y; w[4*k+2] = w4.z; w[4*k+3] = w4.w;
        }
    }

    float z   = latent[zi[b] * EMBED + e];
    float bte = bt[e];
    zb[0][e] = z;
    __syncthreads();

    for (int t = 0; t < NSTEP; t++) {
        int cur = t & 1;
        float zc = zb[cur][e];
        int o = (b * NSTEP + t) * EMBED + e;
        g_zs [o] = zc;                       // emit BEFORE update (scan semantics)
        g_zsh[o] = __float2half(zc);

        const float4* zv = reinterpret_cast<const float4*>(zb[cur]);
        float a0 = 0.f, a1 = 0.f, a2 = 0.f, a3 = 0.f;
        #pragma unroll
        for (int k = 0; k < EMBED / 4; k++) {
            float4 z4 = zv[k];               // broadcast LDS
            a0 = fmaf(w[4*k+0], z4.x, a0);
            a1 = fmaf(w[4*k+1], z4.y, a1);
            a2 = fmaf(w[4*k+2], z4.z, a2);
            a3 = fmaf(w[4*k+3], z4.w, a3);
        }
        float zn = tanhf(zc + (a0 + a1) + (a2 + a3) + bte);
        zb[cur ^ 1][e] = zn;
        __syncthreads();
    }
}

// ---------------- kernel 2: fused logits GEMM + sum(exp), fp16 --------------
// m16n8k16 f16.f16.f16.f16: D fragment = 2 packed regs -> accumulators drop
// 64 -> 32 regs, so the whole hot set (~140) fits the 170-reg cap at
// __launch_bounds__(128, 3) WITHOUT the spills that sank R14.
// Epilogue: D already f16x2 -> HFMA2 (x log2e, + bv*log2e) -> ex2.f16x2,
// accumulated into f32 sums. NSPLIT=14 -> grid 448 ~ 3 CTAs/SM in one wave.
__global__ void __launch_bounds__(128, 3) lse_kernel() {
    __shared__ __align__(16) __half Bs[2][NTILE * BSTRIDE];
    __shared__ __align__(16) __half bvs[2][NTILE];

    const int tid  = threadIdx.x;
    const int w    = tid >> 5;      // 0..3
    const int lane = tid & 31;
    const int g    = lane >> 2;     // 0..7
    const int q    = lane & 3;      // 0..3
    const int rt   = blockIdx.x;
    const int sp   = blockIdx.y;

    // ---- A fragments: 2 m16-tiles x 8 k-steps x 4 regs = 64 regs, resident
    unsigned Afrag[2][8][4];
    {
        const __half* Z = g_zsh;
        #pragma unroll
        for (int mt = 0; mt < 2; mt++) {
            int r0 = (rt * 128 + w * 32 + mt * 16 + g) * EMBED;
            int r1 = r0 + 8 * EMBED;
            #pragma unroll
            for (int s = 0; s < 8; s++) {
                int k0 = s * 16 + 2 * q;
                Afrag[mt][s][0] = *reinterpret_cast<const unsigned*>(Z + r0 + k0);
                Afrag[mt][s][1] = *reinterpret_cast<const unsigned*>(Z + r1 + k0);
                Afrag[mt][s][2] = *reinterpret_cast<const unsigned*>(Z + r0 + k0 + 8);
                Afrag[mt][s][3] = *reinterpret_cast<const unsigned*>(Z + r1 + k0 + 8);
            }
        }
    }

    const unsigned sbase  = (unsigned)__cvta_generic_to_shared(&Bs[0][0]);
    const unsigned bvbase = (unsigned)__cvta_generic_to_shared(&bvs[0][0]);

    const int count = (NTILES_TOTAL - sp + NSPLIT - 1) / NSPLIT;

    auto issue = [&](int i, int buf) {
        int vbase = (sp + i * NSPLIT) * NTILE;
        const __half* src0 = g_Wvh + (size_t)vbase * EMBED;
        #pragma unroll
        for (int c = 0; c < 8; c++) {
            int ch = tid + c * 128;          // 0..1023 16B chunks
            int vr = ch >> 4;
            int kc = ch & 15;
            unsigned dst = sbase + buf * (NTILE * BSTRIDE * 2)
                         + (vr * BSTRIDE + kc * 8) * 2;
            const void* src = src0 + vr * EMBED + kc * 8;
            asm volatile("cp.async.cg.shared.global [%0], [%1], 16;\n"
                         :: "r"(dst), "l"(src));
        }
        if (tid < 8) {
            unsigned dst = bvbase + buf * (NTILE * 2) + tid * 16;
            const void* src = g_bvh + vbase + tid * 8;
            asm volatile("cp.async.cg.shared.global [%0], [%1], 16;\n"
                         :: "r"(dst), "l"(src));
        }
        asm volatile("cp.async.commit_group;\n");
    };

    float sum[2][2] = {{0.f, 0.f}, {0.f, 0.f}};
    const __half2 l2e2 = __float2half2_rn(LOG2E_F);

    issue(0, 0);
    for (int i = 0; i < count; i++) {
        const int buf = i & 1;
        if (i + 1 < count) {
            issue(i + 1, buf ^ 1);
            asm volatile("cp.async.wait_group 1;\n" ::: "memory");
        } else {
            asm volatile("cp.async.wait_group 0;\n" ::: "memory");
        }
        __syncthreads();

        unsigned d[2][8][2];                 // f16x2 accumulators: 32 regs
        #pragma unroll
        for (int mt = 0; mt < 2; mt++)
            #pragma unroll
            for (int j = 0; j < 8; j++) { d[mt][j][0] = 0u; d[mt][j][1] = 0u; }

        const unsigned rowoff  = (unsigned)((lane & 7) * (BSTRIDE * 2) + (lane >> 3) * 16);
        const unsigned bufbase = sbase + buf * (NTILE * BSTRIDE * 2) + rowoff;

        #pragma unroll
        for (int s2 = 0; s2 < 4; s2++) {        // k32 chunks
            #pragma unroll
            for (int j = 0; j < 8; j++) {       // n8 groups
                unsigned b0, b1, b2, b3;
                asm volatile(
                    "ldmatrix.sync.aligned.m8n8.x4.shared.b16 {%0,%1,%2,%3}, [%4];\n"
                    : "=r"(b0), "=r"(b1), "=r"(b2), "=r"(b3)
                    : "r"(bufbase + (unsigned)(j * 8 * (BSTRIDE * 2)) + s2 * 64));
                #pragma unroll
                for (int mt = 0; mt < 2; mt++) {
                    asm volatile(
                        "mma.sync.aligned.m16n8k16.row.col.f16.f16.f16.f16 "
                        "{%0,%1}, {%2,%3,%4,%5}, {%6,%7}, {%0,%1};\n"
                        : "+r"(d[mt][j][0]), "+r"(d[mt][j][1])
                        : "r"(Afrag[mt][2*s2][0]), "r"(Afrag[mt][2*s2][1]),
                          "r"(Afrag[mt][2*s2][2]), "r"(Afrag[mt][2*s2][3]),
                          "r"(b0), "r"(b1));
                    asm volatile(
                        "mma.sync.aligned.m16n8k16.row.col.f16.f16.f16.f16 "
                        "{%0,%1}, {%2,%3,%4,%5}, {%6,%7}, {%0,%1};\n"
                        : "+r"(d[mt][j][0]), "+r"(d[mt][j][1])
                        : "r"(Afrag[mt][2*s2+1][0]), "r"(Afrag[mt][2*s2+1][1]),
                          "r"(Afrag[mt][2*s2+1][2]), "r"(Afrag[mt][2*s2+1][3]),
                          "r"(b2), "r"(b3));
                }
            }
        }

        // epilogue: f16x2 logits -> HFMA2 -> ex2.f16x2 -> f32 sums
        #pragma unroll
        for (int j = 0; j < 8; j++) {
            __half2 bv2 = reinterpret_cast<const __half2*>(&bvs[buf][0])[j * 4 + q];
            #pragma unroll
            for (int mt = 0; mt < 2; mt++) {
                __half2 l0 = __hfma2(*reinterpret_cast<__half2*>(&d[mt][j][0]), l2e2, bv2);
                __half2 l1 = __hfma2(*reinterpret_cast<__half2*>(&d[mt][j][1]), l2e2, bv2);
                unsigned p0 = ex2_h2(*reinterpret_cast<unsigned*>(&l0));
                unsigned p1 = ex2_h2(*reinterpret_cast<unsigned*>(&l1));
                float2 e0 = __half22float2(*reinterpret_cast<__half2*>(&p0));
                float2 e1 = __half22float2(*reinterpret_cast<__half2*>(&p1));
                sum[mt][0] += e0.x + e0.y;
                sum[mt][1] += e1.x + e1.y;
            }
        }
        __syncthreads();
    }

    // reduce over the 4 q-threads holding the same rows
    #pragma unroll
    for (int mt = 0; mt < 2; mt++) {
        float s0 = sum[mt][0], s1 = sum[mt][1];
        s0 += __shfl_xor_sync(0xffffffffu, s0, 1);
        s0 += __shfl_xor_sync(0xffffffffu, s0, 2);
        s1 += __shfl_xor_sync(0xffffffffu, s1, 1);
        s1 += __shfl_xor_sync(0xffffffffu, s1, 2);
        if (q == 0) {
            int r = rt * 128 + w * 32 + mt * 16 + g;
            g_S[sp * ROWS + r]     = s0;
            g_S[sp * ROWS + r + 8] = s1;
        }
    }
}

// ---------------- kernel 3: gathered logit l_y (exact fp32) -----------------
__global__ void __launch_bounds__(256) ly_kernel(const int*   __restrict__ y,
                                                 const float* __restrict__ Wv,
                                                 const float* __restrict__ bv) {
    int gw   = (blockIdx.x * blockDim.x + threadIdx.x) >> 5;  // 0..4095
    int lane = threadIdx.x & 31;
    int col  = y[gw];
    const float4* zz = reinterpret_cast<const float4*>(g_zs) + gw * 32 + lane;
    const float4* ww = reinterpret_cast<const float4*>(Wv) + (size_t)col * 32 + lane;
    float4 a = *zz;
    float4 bb = __ldg(ww);
    float p = a.x * bb.x + a.y * bb.y + a.z * bb.z + a.w * bb.w;
    #pragma unroll
    for (int o = 16; o; o >>= 1) p += __shfl_xor_sync(0xffffffffu, p, o);
    if (lane == 0) g_ly[gw] = p + bv[col];
}

// ---------------- kernel 4: combine -----------------------------------------
__global__ void combine_kernel(float* __restrict__ out) {
    int r = blockIdx.x * blockDim.x + threadIdx.x;
    if (r < ROWS) {
        float s = 0.f;
        #pragma unroll
        for (int i = 0; i < NSPLIT; i++) s += g_S[i * ROWS + r];
        out[r] = g_ly[r] - logf(s);
    }
}

// ---------------- launch -----------------------------------------------------
extern "C" void kernel_launch(void* const* d_in, const int* in_sizes, int n_in,
                              void* d_out, int out_size) {
    const int*   zi     = (const int*)  d_in[0];
    const int*   y      = (const int*)  d_in[1];
    const float* latent = (const float*)d_in[2];
    const float* Wt     = (const float*)d_in[3];
    const float* bt     = (const float*)d_in[4];
    const float* Wv     = (const float*)d_in[5];
    const float* bv     = (const float*)d_in[6];
    float* out = (float*)d_out;

    convert_kernel<<<(VPAD * EMBED + 255) / 256, 256>>>(Wv, bv);
    rnn_kernel<<<BATCH, EMBED>>>(zi, latent, Wt, bt);
    ly_kernel<<<ROWS / 8, 256>>>(y, Wv, bv);
    lse_kernel<<<dim3(32, NSPLIT), 128>>>();
    combine_kernel<<<(ROWS + 255) / 256, 256>>>(out);
}